// round 2
// baseline (speedup 1.0000x reference)
#include <cuda_runtime.h>

// Problem constants (fixed by the reference)
#define NB    32
#define NH    64
#define NW    64
#define NT    100
#define COUT  8
#define KS    6
#define LP    2   // left/top pad

// Tiling
#define TILE_W 16
#define TILE_H 8
#define HALO_W (TILE_W + KS - 1)   // 21
#define HALO_H (TILE_H + KS - 1)   // 13
#define CHUNK  4                   // timesteps per chunk (float4 I/O); 100 % 4 == 0
#define NTHR   (TILE_W * TILE_H)   // 128

typedef unsigned long long u64;

// ---- packed fp32x2 helpers (Blackwell FFMA2 path) ----
__device__ __forceinline__ u64 pk2(float lo, float hi) {
    u64 r; asm("mov.b64 %0, {%1, %2};" : "=l"(r) : "f"(lo), "f"(hi)); return r;
}
__device__ __forceinline__ void upk2(u64 v, float& lo, float& hi) {
    asm("mov.b64 {%0, %1}, %2;" : "=f"(lo), "=f"(hi) : "l"(v));
}
__device__ __forceinline__ u64 fma2(u64 a, u64 b, u64 c) {
    u64 d; asm("fma.rn.f32x2 %0, %1, %2, %3;" : "=l"(d) : "l"(a), "l"(b), "l"(c)); return d;
}

__global__ __launch_bounds__(NTHR)
void sconv_spike_kernel(const float* __restrict__ x,
                        const float* __restrict__ w,
                        const float* __restrict__ thr_p,
                        float* __restrict__ out)
{
    __shared__ float4 sx[HALO_H][HALO_W];        // input tile (4 timesteps packed)
    __shared__ float2 sw2[COUT * KS * KS];       // weights duplicated (w, w)

    const int tx  = threadIdx.x;
    const int ty  = threadIdx.y;
    const int tid = ty * TILE_W + tx;
    const int b   = blockIdx.z;
    const int h0  = blockIdx.y * TILE_H;
    const int w0  = blockIdx.x * TILE_W;

    // load weights once, duplicated into both f32x2 lanes
    for (int i = tid; i < COUT * KS * KS; i += NTHR) {
        float v = w[i];
        sw2[i] = make_float2(v, v);
    }
    const float thr = thr_p[0];

    const int h = h0 + ty;
    const int wq = w0 + tx;

    float ut[COUT];
#pragma unroll
    for (int c = 0; c < COUT; c++) ut[c] = 0.0f;

    const float* xbase = x + (size_t)b * NH * NW * NT;
    float* obase = out + (size_t)b * COUT * NH * NW * NT
                       + ((size_t)h * NW + wq) * NT;

    for (int t0 = 0; t0 < NT; t0 += CHUNK) {
        __syncthreads();   // also covers initial weight-load visibility
        // cooperative halo-tile load: float4 = timesteps [t0, t0+4)
        for (int i = tid; i < HALO_H * HALO_W; i += NTHR) {
            int r = i / HALO_W, c = i % HALO_W;
            int gh = h0 - LP + r;
            int gw = w0 - LP + c;
            float4 v = make_float4(0.f, 0.f, 0.f, 0.f);
            if (gh >= 0 && gh < NH && gw >= 0 && gw < NW)
                v = *(const float4*)(xbase + ((size_t)gh * NW + gw) * NT + t0);
            sx[r][c] = v;
        }
        __syncthreads();

        // conv: 8 couts x 4 timesteps as 2 packed f32x2 accumulators per cout
        u64 acc01[COUT], acc23[COUT];
#pragma unroll
        for (int c = 0; c < COUT; c++) { acc01[c] = 0ull; acc23[c] = 0ull; }

#pragma unroll
        for (int kh = 0; kh < KS; kh++) {
#pragma unroll
            for (int kw = 0; kw < KS; kw++) {
                const u64* xp = (const u64*)&sx[ty + kh][tx + kw];
                u64 x01 = xp[0];
                u64 x23 = xp[1];
#pragma unroll
                for (int c = 0; c < COUT; c++) {
                    u64 w2 = *(const u64*)&sw2[c * (KS * KS) + kh * KS + kw];
                    acc01[c] = fma2(x01, w2, acc01[c]);
                    acc23[c] = fma2(x23, w2, acc23[c]);
                }
            }
        }

        // recurrence (exact elementwise order of the reference) + coalesced-ish store
#pragma unroll
        for (int c = 0; c < COUT; c++) {
            float wx0, wx1, wx2, wx3;
            upk2(acc01[c], wx0, wx1);
            upk2(acc23[c], wx2, wx3);
            float u = ut[c];
            // st_prev == (u > 0); ut = (ut - st*thr) + wx; st = (ut > 0)
            u = (u - (u > 0.f ? thr : 0.f)) + wx0; float s0 = (u > 0.f) ? 1.f : 0.f;
            u = (u - (u > 0.f ? thr : 0.f)) + wx1; float s1 = (u > 0.f) ? 1.f : 0.f;
            u = (u - (u > 0.f ? thr : 0.f)) + wx2; float s2 = (u > 0.f) ? 1.f : 0.f;
            u = (u - (u > 0.f ? thr : 0.f)) + wx3; float s3 = (u > 0.f) ? 1.f : 0.f;
            ut[c] = u;
            *(float4*)(obase + (size_t)c * NH * NW * NT + t0) =
                make_float4(s0, s1, s2, s3);
        }
    }
}

extern "C" void kernel_launch(void* const* d_in, const int* in_sizes, int n_in,
                              void* d_out, int out_size)
{
    const float* x    = (const float*)d_in[0];  // [32,1,64,64,100]
    const float* w    = (const float*)d_in[1];  // [8,1,6,6]
    const float* thr  = (const float*)d_in[2];  // [1]
    float* out = (float*)d_out;                 // [32,8,64,64,100]

    dim3 block(TILE_W, TILE_H, 1);
    dim3 grid(NW / TILE_W, NH / TILE_H, NB);    // (4, 8, 32)
    sconv_spike_kernel<<<grid, block>>>(x, w, thr, out);
}

// round 3
// speedup vs baseline: 1.7633x; 1.7633x over previous
#include <cuda_runtime.h>

// Problem constants
#define NB    32
#define NH    64
#define NW    64
#define NT    100
#define COUT  8
#define KS    6
#define LP    2

// Tiling
#define TILE_W 16
#define TILE_H 8
#define HALO_W (TILE_W + KS - 1)   // 21
#define HALO_H (TILE_H + KS - 1)   // 13
#define NPIX   (HALO_W * HALO_H)   // 273
#define NTHR   256                 // 16 x 8 x 2 (cout split)
#define CPT    4                   // couts per thread
#define NCH8   12                  // 12 chunks of 8 timesteps, + 1 tail chunk of 4
#define NHWT   (NH * NW * NT)      // 409600

typedef unsigned long long u64;

__device__ __forceinline__ void upk2(u64 v, float& lo, float& hi) {
    asm("mov.b64 {%0, %1}, %2;" : "=f"(lo), "=f"(hi) : "l"(v));
}
__device__ __forceinline__ u64 fma2(u64 a, u64 b, u64 c) {
    u64 d; asm("fma.rn.f32x2 %0, %1, %2, %3;" : "=l"(d) : "l"(a), "l"(b), "l"(c)); return d;
}
__device__ __forceinline__ unsigned smem_u32(const void* p) {
    return (unsigned)__cvta_generic_to_shared(p);
}
__device__ __forceinline__ void cp16(unsigned dst, const void* src) {
    asm volatile("cp.async.ca.shared.global [%0], [%1], 16;" :: "r"(dst), "l"(src));
}
__device__ __forceinline__ void cp_commit() { asm volatile("cp.async.commit_group;" ::: "memory"); }
__device__ __forceinline__ void cp_wait1()  { asm volatile("cp.async.wait_group 1;" ::: "memory"); }
__device__ __forceinline__ void cp_wait0()  { asm volatile("cp.async.wait_group 0;" ::: "memory"); }

// exact reference recurrence step: ut = (ut - st_prev*thr) + wx ; st = (ut > 0)
__device__ __forceinline__ float stepf(float& u, float wx, float thr) {
    u = (u - (u > 0.f ? thr : 0.f)) + wx;
    return (u > 0.f) ? 1.f : 0.f;
}

__global__ __launch_bounds__(NTHR)
void sconv_spike_kernel(const float* __restrict__ x,
                        const float* __restrict__ w,
                        const float* __restrict__ thr_p,
                        float* __restrict__ out)
{
    // double-buffered input tile: per pixel 4 u64 = 32B = 8 timesteps
    __shared__ u64 sx[2][NPIX * 4];
    __shared__ u64 sw2[COUT * KS * KS];   // weight duplicated into both f32x2 lanes

    const int tx  = threadIdx.x;
    const int ty  = threadIdx.y;
    const int cz  = threadIdx.z;          // cout half: couts [cz*4, cz*4+4)
    const int tid = tx + TILE_W * ty + (TILE_W * TILE_H) * cz;
    const int b   = blockIdx.z;
    const int h0  = blockIdx.y * TILE_H;
    const int w0  = blockIdx.x * TILE_W;

    // weights, duplicated (w, w) for f32x2
    for (int i = tid; i < COUT * KS * KS; i += NTHR) {
        unsigned bits = __float_as_uint(w[i]);
        sw2[i] = ((u64)bits << 32) | (u64)bits;
    }
    // zero OOB halo pixels once (they never change across chunks)
    for (int pix = tid; pix < NPIX; pix += NTHR) {
        int r = pix / HALO_W, c = pix % HALO_W;
        int gh = h0 - LP + r, gw = w0 - LP + c;
        if (gh < 0 || gh >= NH || gw < 0 || gw >= NW) {
#pragma unroll
            for (int j = 0; j < 4; j++) { sx[0][pix * 4 + j] = 0ull; sx[1][pix * 4 + j] = 0ull; }
        }
    }
    const float thr = thr_p[0];

    const float* xb = x + (size_t)b * NH * NW * NT;
    const int h  = h0 + ty;
    const int wq = w0 + tx;
    const int cbase = cz * CPT;
    float* obase = out + (size_t)b * COUT * NHWT
                       + ((size_t)h * NW + wq) * NT
                       + (size_t)cbase * NHWT;

    float ut[CPT];
#pragma unroll
    for (int c = 0; c < CPT; c++) ut[c] = 0.f;

    // chunk loader: nf4 float4's (= nf4*4 timesteps) per pixel into buffer `buf`
    auto load_chunk = [&](int buf, int t0, int nf4) {
        int total = NPIX * nf4;
        for (int idx = tid; idx < total; idx += NTHR) {
            int pix = (nf4 == 2) ? (idx >> 1) : idx;
            int j   = (nf4 == 2) ? (idx & 1) : 0;
            int r = pix / HALO_W, c = pix % HALO_W;
            int gh = h0 - LP + r, gw = w0 - LP + c;
            if (gh >= 0 && gh < NH && gw >= 0 && gw < NW) {
                const float* src = xb + ((size_t)gh * NW + gw) * NT + t0 + j * 4;
                cp16(smem_u32(&sx[buf][pix * 4 + j * 2]), src);
            }
        }
        cp_commit();
    };

    // ---- software pipeline: prefetch chunk i+1 while computing chunk i ----
    load_chunk(0, 0, 2);

#pragma unroll 1
    for (int i = 0; i < NCH8; i++) {
        const int t0  = i * 8;
        const int buf = i & 1;
        if (i + 1 < NCH8) load_chunk((i + 1) & 1, t0 + 8, 2);
        else              load_chunk((i + 1) & 1, 96, 1);   // tail prefetch
        cp_wait1();
        __syncthreads();

        u64 a0[CPT], a1[CPT], a2[CPT], a3[CPT];
#pragma unroll
        for (int c = 0; c < CPT; c++) { a0[c] = 0; a1[c] = 0; a2[c] = 0; a3[c] = 0; }

#pragma unroll
        for (int kh = 0; kh < KS; kh++) {
#pragma unroll
            for (int kw = 0; kw < KS; kw++) {
                const u64* xp = &sx[buf][((ty + kh) * HALO_W + (tx + kw)) * 4];
                u64 x0 = xp[0], x1 = xp[1], x2 = xp[2], x3 = xp[3];
#pragma unroll
                for (int c = 0; c < CPT; c++) {
                    u64 w2 = sw2[(cbase + c) * (KS * KS) + kh * KS + kw];
                    a0[c] = fma2(x0, w2, a0[c]);
                    a1[c] = fma2(x1, w2, a1[c]);
                    a2[c] = fma2(x2, w2, a2[c]);
                    a3[c] = fma2(x3, w2, a3[c]);
                }
            }
        }

#pragma unroll
        for (int c = 0; c < CPT; c++) {
            float wx0, wx1, wx2, wx3, wx4, wx5, wx6, wx7;
            upk2(a0[c], wx0, wx1); upk2(a1[c], wx2, wx3);
            upk2(a2[c], wx4, wx5); upk2(a3[c], wx6, wx7);
            float u = ut[c];
            float s0 = stepf(u, wx0, thr), s1 = stepf(u, wx1, thr);
            float s2 = stepf(u, wx2, thr), s3 = stepf(u, wx3, thr);
            float s4 = stepf(u, wx4, thr), s5 = stepf(u, wx5, thr);
            float s6 = stepf(u, wx6, thr), s7 = stepf(u, wx7, thr);
            ut[c] = u;
            float4* p = (float4*)(obase + (size_t)c * NHWT + t0);
            p[0] = make_float4(s0, s1, s2, s3);   // 32B contiguous -> full sector
            p[1] = make_float4(s4, s5, s6, s7);
        }
        __syncthreads();   // done reading buf; next iter may overwrite it
    }

    // ---- tail chunk: t = 96..99 (prefetched into buf (NCH8 & 1)) ----
    {
        const int buf = NCH8 & 1;
        cp_wait0();
        __syncthreads();

        u64 a0[CPT], a1[CPT];
#pragma unroll
        for (int c = 0; c < CPT; c++) { a0[c] = 0; a1[c] = 0; }
#pragma unroll
        for (int kh = 0; kh < KS; kh++) {
#pragma unroll
            for (int kw = 0; kw < KS; kw++) {
                const u64* xp = &sx[buf][((ty + kh) * HALO_W + (tx + kw)) * 4];
                u64 x0 = xp[0], x1 = xp[1];
#pragma unroll
                for (int c = 0; c < CPT; c++) {
                    u64 w2 = sw2[(cbase + c) * (KS * KS) + kh * KS + kw];
                    a0[c] = fma2(x0, w2, a0[c]);
                    a1[c] = fma2(x1, w2, a1[c]);
                }
            }
        }
#pragma unroll
        for (int c = 0; c < CPT; c++) {
            float wx0, wx1, wx2, wx3;
            upk2(a0[c], wx0, wx1); upk2(a1[c], wx2, wx3);
            float u = ut[c];
            float s0 = stepf(u, wx0, thr), s1 = stepf(u, wx1, thr);
            float s2 = stepf(u, wx2, thr), s3 = stepf(u, wx3, thr);
            ut[c] = u;
            *(float4*)(obase + (size_t)c * NHWT + 96) = make_float4(s0, s1, s2, s3);
        }
    }
}

extern "C" void kernel_launch(void* const* d_in, const int* in_sizes, int n_in,
                              void* d_out, int out_size)
{
    const float* x   = (const float*)d_in[0];  // [32,1,64,64,100]
    const float* w   = (const float*)d_in[1];  // [8,1,6,6]
    const float* thr = (const float*)d_in[2];  // [1]
    float* out = (float*)d_out;                // [32,8,64,64,100]

    dim3 block(TILE_W, TILE_H, 2);             // 256 threads, cout split on z
    dim3 grid(NW / TILE_W, NH / TILE_H, NB);   // (4, 8, 32)
    sconv_spike_kernel<<<grid, block>>>(x, w, thr, out);
}